// round 8
// baseline (speedup 1.0000x reference)
#include <cuda_runtime.h>
#include <math.h>

#define NN 8192

// Scratch: one partial per half-row + an arrival counter per row.
// Counters are zero-initialized at load and reset to 0 by the finishing CTA,
// so every launch (and every graph replay) sees the same initial state.
__device__ float g_partial[2 * NN];
__device__ unsigned int g_count[NN];

__device__ __forceinline__ float4 ldg_stream_noL1(const float4* p) {
    float4 r;
    asm("ld.global.nc.L1::no_allocate.v4.f32 {%0,%1,%2,%3}, [%4];"
        : "=f"(r.x), "=f"(r.y), "=f"(r.z), "=f"(r.w)
        : "l"(p));
    return r;
}

// Half-row streaming + fused last-arriver epilogue.
// grid = 16384 CTAs (2 per row), 256 threads, 4 front-batched 128-bit w-loads
// per thread. The CTA whose partial lands second runs the Izhikevich pointwise
// update for its row (one thread), fully overlapped with other CTAs' streaming.
__global__ void __launch_bounds__(256, 8) izh_fused_kernel(
    const float* __restrict__ x_in,
    const float* __restrict__ v,
    const float* __restrict__ u,
    const float* __restrict__ g,
    const float* __restrict__ w,
    const float* __restrict__ a_p,
    const float* __restrict__ b_p,
    const float* __restrict__ c_p,
    const float* __restrict__ d_p,
    float* __restrict__ out)
{
    const int bid  = blockIdx.x;
    const int row  = bid >> 1;
    const int half = bid & 1;
    const int base = half * 1024;  // float4 units; a full row is 2048 float4

    const float4* __restrict__ wrow = reinterpret_cast<const float4*>(w + (size_t)row * NN);
    const float4* __restrict__ g4   = reinterpret_cast<const float4*>(g);

    float sum = 0.0f;
    #pragma unroll
    for (int i = 0; i < 4; ++i) {
        const int idx = base + threadIdx.x + i * 256;
        const float4 a = ldg_stream_noL1(&wrow[idx]);  // streaming, no L1 alloc
        const float4 b = __ldg(&g4[idx]);              // L1-resident
        sum += a.x * b.x;
        sum += a.y * b.y;
        sum += a.z * b.z;
        sum += a.w * b.w;
    }

    #pragma unroll
    for (int off = 16; off > 0; off >>= 1)
        sum += __shfl_xor_sync(0xffffffffu, sum, off);

    __shared__ float ssum[8];
    const int wid = threadIdx.x >> 5;
    if ((threadIdx.x & 31) == 0) ssum[wid] = sum;
    __syncthreads();

    if (threadIdx.x == 0) {
        float dot = 0.0f;
        #pragma unroll
        for (int i = 0; i < 8; ++i) dot += ssum[i];

        // Publish partial, then signal arrival (release).
        g_partial[bid] = dot;
        __threadfence();
        const unsigned int old = atomicAdd(&g_count[row], 1u);

        if (old == 1u) {
            // Last arriver: acquire, read sibling partial, run epilogue.
            __threadfence();
            const float other = g_partial[bid ^ 1];

            // float add is commutative -> bit-identical regardless of order.
            const float I  = dot + other + __ldg(&x_in[row]);
            const float vv = __ldg(&v[row]);
            const float uu = __ldg(&u[row]);
            const float gg = __ldg(&g[row]);

            // Izhikevich quadratic dynamics
            const float v1 = vv + (0.04f * vv * vv + 5.0f * vv + 140.0f - uu + I);

            // differentiable spike surrogate: sigmoid(4 * (v1 - 30))
            const float s = 1.0f / (1.0f + expf(-4.0f * (v1 - 30.0f)));

            // hard spike mask for state resets
            const float spk = (v1 >= 30.0f) ? 1.0f : 0.0f;
            const float ns  = 1.0f - spk;

            const float du = fabsf(__ldg(&a_p[row])) * (fabsf(__ldg(&b_p[row])) * v1 - uu);
            const float dg = -gg / 6.5f;

            out[row]           = ns * v1 + spk * __ldg(&c_p[row]);   // v_out
            out[NN + row]      = s;                                   // spiked_s
            out[2 * NN + row]  = ns * (uu + du) + spk * __ldg(&d_p[row]); // u_out
            out[3 * NN + row]  = ns * (gg + dg) + spk;                // g_out

            // Reset counter so the next launch / graph replay sees 0.
            g_count[row] = 0u;
        }
    }
}

extern "C" void kernel_launch(void* const* d_in, const int* in_sizes, int n_in,
                              void* d_out, int out_size)
{
    const float* x_in = (const float*)d_in[0];
    const float* v    = (const float*)d_in[1];
    const float* u    = (const float*)d_in[2];
    const float* g    = (const float*)d_in[3];
    const float* w    = (const float*)d_in[4];
    const float* a_p  = (const float*)d_in[5];
    const float* b_p  = (const float*)d_in[6];
    const float* c_p  = (const float*)d_in[7];
    const float* d_p  = (const float*)d_in[8];
    float* out = (float*)d_out;

    izh_fused_kernel<<<2 * NN, 256>>>(x_in, v, u, g, w, a_p, b_p, c_p, d_p, out);
}

// round 9
// speedup vs baseline: 1.0985x; 1.0985x over previous
#include <cuda_runtime.h>
#include <math.h>

#define NN 8192

// Partial dot products: one float2 per row (half0, half1). Written by the dot
// kernel, consumed by the PDL-overlapped epilogue. Static device memory.
__device__ float2 g_partial[NN];

__device__ __forceinline__ float4 ldg_stream_noL1(const float4* p) {
    float4 r;
    asm("ld.global.nc.L1::no_allocate.v4.f32 {%0,%1,%2,%3}, [%4];"
        : "=f"(r.x), "=f"(r.y), "=f"(r.z), "=f"(r.w)
        : "l"(p));
    return r;
}

// k1: half-row streaming. 16384 CTAs (2 per row), 256 threads, 4 front-batched
// 128-bit w-loads per thread. No fences, no atomics; partial -> scratch, then
// PDL trigger so the epilogue can launch while this kernel drains.
__global__ void __launch_bounds__(256, 8) izh_dot_kernel(
    const float* __restrict__ g,
    const float* __restrict__ w)
{
    const int bid  = blockIdx.x;
    const int row  = bid >> 1;
    const int half = bid & 1;
    const int base = half * 1024;  // float4 units; a full row is 2048 float4

    const float4* __restrict__ wrow = reinterpret_cast<const float4*>(w + (size_t)row * NN);
    const float4* __restrict__ g4   = reinterpret_cast<const float4*>(g);

    float sum = 0.0f;
    #pragma unroll
    for (int i = 0; i < 4; ++i) {
        const int idx = base + threadIdx.x + i * 256;
        const float4 a = ldg_stream_noL1(&wrow[idx]);  // streaming, no L1 alloc
        const float4 b = __ldg(&g4[idx]);              // L1-resident
        sum += a.x * b.x;
        sum += a.y * b.y;
        sum += a.z * b.z;
        sum += a.w * b.w;
    }

    #pragma unroll
    for (int off = 16; off > 0; off >>= 1)
        sum += __shfl_xor_sync(0xffffffffu, sum, off);

    __shared__ float ssum[8];
    const int wid = threadIdx.x >> 5;
    if ((threadIdx.x & 31) == 0) ssum[wid] = sum;
    __syncthreads();

    if (threadIdx.x == 0) {
        float dot = 0.0f;
        #pragma unroll
        for (int i = 0; i < 8; ++i) dot += ssum[i];
        reinterpret_cast<float*>(g_partial)[bid] = dot;
    }
    __syncthreads();  // partial store visible to whole CTA before trigger
    cudaTriggerProgrammaticLaunchCompletion();
}

// k2: pointwise Izhikevich epilogue, PDL-launched. Independent input loads are
// issued BEFORE the grid-dependency wait so they overlap k1's tail; partials
// are read (coalesced float2) only after the wait.
__global__ void __launch_bounds__(128) izh_epilogue_kernel(
    const float* __restrict__ x_in,
    const float* __restrict__ v,
    const float* __restrict__ u,
    const float* __restrict__ g,
    const float* __restrict__ a_p,
    const float* __restrict__ b_p,
    const float* __restrict__ c_p,
    const float* __restrict__ d_p,
    float* __restrict__ out)
{
    const int r = blockIdx.x * 128 + threadIdx.x;

    // Independent of k1 — issue before the dependency wait.
    const float xx = x_in[r];
    const float vv = v[r];
    const float uu = u[r];
    const float gg = g[r];
    const float aa = a_p[r];
    const float bb = b_p[r];
    const float cc = c_p[r];
    const float dd = d_p[r];

    cudaGridDependencySynchronize();

    const float2 p = g_partial[r];
    const float I  = p.x + p.y + xx;

    // Izhikevich quadratic dynamics
    const float v1 = vv + (0.04f * vv * vv + 5.0f * vv + 140.0f - uu + I);

    // differentiable spike surrogate: sigmoid(4 * (v1 - 30))
    const float s = 1.0f / (1.0f + expf(-4.0f * (v1 - 30.0f)));

    // hard spike mask for state resets
    const float spk = (v1 >= 30.0f) ? 1.0f : 0.0f;
    const float ns  = 1.0f - spk;

    const float du = fabsf(aa) * (fabsf(bb) * v1 - uu);
    const float dg = -gg / 6.5f;

    out[r]           = ns * v1 + spk * cc;            // v_out
    out[NN + r]      = s;                              // spiked_s
    out[2 * NN + r]  = ns * (uu + du) + spk * dd;      // u_out
    out[3 * NN + r]  = ns * (gg + dg) + spk;           // g_out
}

extern "C" void kernel_launch(void* const* d_in, const int* in_sizes, int n_in,
                              void* d_out, int out_size)
{
    const float* x_in = (const float*)d_in[0];
    const float* v    = (const float*)d_in[1];
    const float* u    = (const float*)d_in[2];
    const float* g    = (const float*)d_in[3];
    const float* w    = (const float*)d_in[4];
    const float* a_p  = (const float*)d_in[5];
    const float* b_p  = (const float*)d_in[6];
    const float* c_p  = (const float*)d_in[7];
    const float* d_p  = (const float*)d_in[8];
    float* out = (float*)d_out;

    izh_dot_kernel<<<2 * NN, 256>>>(g, w);

    // Epilogue with programmatic dependent launch: overlaps k1's drain.
    cudaLaunchAttribute attr;
    attr.id = cudaLaunchAttributeProgrammaticStreamSerialization;
    attr.val.programmaticStreamSerializationAllowed = 1;

    cudaLaunchConfig_t cfg = {};
    cfg.gridDim = dim3(NN / 128);
    cfg.blockDim = dim3(128);
    cfg.dynamicSmemBytes = 0;
    cfg.stream = 0;  // legacy default stream (same as <<<>>> above)
    cfg.attrs = &attr;
    cfg.numAttrs = 1;

    cudaLaunchKernelEx(&cfg, izh_epilogue_kernel,
                       x_in, v, u, g, a_p, b_p, c_p, d_p, out);
}